// round 13
// baseline (speedup 1.0000x reference)
#include <cuda_runtime.h>
#include <stdint.h>

// Problem shape (fixed): N=100000, E=3200000, C_in=128, C_hid=16, C_out=128
#define MAXN 100096
#define MAXE 3400000

// Device scratch (static; no allocations). g_deg is zero at load (BSS) and
// restored to zero by k_gather2 every invocation (self-cleaning).
__device__ int    g_deg[MAXN];        // dst in-degree (no self loop)
__device__ int    g_rowptr[MAXN];     // CSR row start; after k_fill = row END
__device__ int    g_bsum[512];        // scan block sums
__device__ int    g_csrc[MAXE];       // CSR: src node per edge, grouped by dst
__device__ float  g_dinv[MAXN];       // 1/sqrt(deg+1)
__device__ float4 g_h1s[MAXN * 4];    // (X @ W1) * dinv      (16 f/node)
__device__ float4 g_h2s[MAXN * 4];    // relu(dinv*agg1 + b1) * dinv

// Packed f32x2 helpers (Blackwell dual-fp32 pipe)
#define PACKX2(out, lo, hi) \
    asm("mov.b64 %0, {%1, %2};" : "=l"(out) : "f"(lo), "f"(hi))
#define UNPACKX2(lo, hi, in) \
    asm("mov.b64 {%0, %1}, %2;" : "=f"(lo), "=f"(hi) : "l"(in))
#define ADDX2(out, a, b) \
    asm("add.rn.f32x2 %0, %1, %2;" : "=l"(out) : "l"(a), "l"(b))

// ---------------------------------------------------------------------------
// 4 edges per thread via int4 (higher atomic MLP, fewer index loads)
__global__ void k_deg(const int* __restrict__ dst, int E) {
    int i = blockIdx.x * blockDim.x + threadIdx.x;
    int base = i * 4;
    if (base + 3 < E) {
        int4 d = *(const int4*)(dst + base);
        atomicAdd(&g_deg[d.x], 1);
        atomicAdd(&g_deg[d.y], 1);
        atomicAdd(&g_deg[d.z], 1);
        atomicAdd(&g_deg[d.w], 1);
    } else if (base < E) {
        for (int j = base; j < E; j++) atomicAdd(&g_deg[dst[j]], 1);
    }
}

// Block-level exclusive scan (256/block) -> rowptr partial + per-block totals
__global__ void k_scan1(int N) {
    __shared__ int ws[8];
    int i = blockIdx.x * 256 + threadIdx.x;
    int lane = threadIdx.x & 31, wid = threadIdx.x >> 5;
    int v = (i < N) ? g_deg[i] : 0;
    int x = v;
#pragma unroll
    for (int o = 1; o < 32; o <<= 1) {
        int y = __shfl_up_sync(~0u, x, o);
        if (lane >= o) x += y;
    }
    if (lane == 31) ws[wid] = x;
    __syncthreads();
    if (wid == 0) {
        int s = (lane < 8) ? ws[lane] : 0;
#pragma unroll
        for (int o = 1; o < 8; o <<= 1) {
            int y = __shfl_up_sync(~0u, s, o);
            if (lane >= o) s += y;
        }
        if (lane < 8) ws[lane] = s;
    }
    __syncthreads();
    int excl = x - v + (wid ? ws[wid - 1] : 0);
    if (i < N) g_rowptr[i] = excl;
    if (threadIdx.x == 255) g_bsum[blockIdx.x] = ws[7];
}

// Scan the (<=512) block sums, single block.
__global__ void k_scan2(int nb) {
    __shared__ int sm[512];
    int t = threadIdx.x;
    int orig = (t < nb) ? g_bsum[t] : 0;
    sm[t] = orig;
    __syncthreads();
    for (int o = 1; o < 512; o <<= 1) {
        int v = (t >= o) ? sm[t - o] : 0;
        __syncthreads();
        sm[t] += v;
        __syncthreads();
    }
    if (t < nb) g_bsum[t] = sm[t] - orig;
}

// rowptr += block offset (k_fill will advance rowptr itself to row end)
__global__ void k_finish(int N) {
    int i = blockIdx.x * 256 + threadIdx.x;
    if (i < N) g_rowptr[i] += g_bsum[blockIdx.x];
}

// 4 edges per thread via int4; advances g_rowptr (post-fill: rowptr = row end)
__global__ void k_fill(const int* __restrict__ src, const int* __restrict__ dst, int E) {
    int i = blockIdx.x * blockDim.x + threadIdx.x;
    int base = i * 4;
    if (base + 3 < E) {
        int4 s = *(const int4*)(src + base);
        int4 d = *(const int4*)(dst + base);
        int p0 = atomicAdd(&g_rowptr[d.x], 1);
        int p1 = atomicAdd(&g_rowptr[d.y], 1);
        int p2 = atomicAdd(&g_rowptr[d.z], 1);
        int p3 = atomicAdd(&g_rowptr[d.w], 1);
        g_csrc[p0] = s.x;
        g_csrc[p1] = s.y;
        g_csrc[p2] = s.z;
        g_csrc[p3] = s.w;
    } else if (base < E) {
        for (int j = base; j < E; j++) {
            int pos = atomicAdd(&g_rowptr[dst[j]], 1);
            g_csrc[pos] = src[j];
        }
    }
}

// ---------------------------------------------------------------------------
// h1s = (X @ W1) * dinv; also computes g_dinv from g_deg (k_dinv folded in).
__device__ __forceinline__ void fma16(float xs, const float4* __restrict__ w,
                                      float4& a0, float4& a1, float4& a2, float4& a3) {
    float4 w0 = w[0], w1 = w[1], w2 = w[2], w3 = w[3];
    a0.x += xs * w0.x; a0.y += xs * w0.y; a0.z += xs * w0.z; a0.w += xs * w0.w;
    a1.x += xs * w1.x; a1.y += xs * w1.y; a1.z += xs * w1.z; a1.w += xs * w1.w;
    a2.x += xs * w2.x; a2.y += xs * w2.y; a2.z += xs * w2.z; a2.w += xs * w2.w;
    a3.x += xs * w3.x; a3.y += xs * w3.y; a3.z += xs * w3.z; a3.w += xs * w3.w;
}

__global__ void __launch_bounds__(256, 5)
k_gemm1(const float* __restrict__ x, const float* __restrict__ W1, int N) {
    __shared__ float4 Ws[512];        // 128 x 16
    __shared__ float4 Xs[256][5];     // 256 rows x 16 floats (+pad)

    for (int i = threadIdx.x; i < 512; i += 256)
        Ws[i] = ((const float4*)W1)[i];

    int n0 = blockIdx.x * 256;
    int rows = min(256, N - n0);
    int n = n0 + threadIdx.x;
    float4 a0 = {0,0,0,0}, a1 = a0, a2 = a0, a3 = a0;
    const float4* xg = (const float4*)x;

#pragma unroll 1
    for (int c = 0; c < 8; c++) {
        __syncthreads();
#pragma unroll
        for (int i = threadIdx.x; i < 1024; i += 256) {
            int r = i >> 2, q = i & 3;
            if (r < rows)
                Xs[r][q] = xg[(size_t)(n0 + r) * 32 + c * 4 + q];
        }
        __syncthreads();
        if (threadIdx.x < rows) {
#pragma unroll
            for (int q = 0; q < 4; q++) {
                float4 xv = Xs[threadIdx.x][q];
                int kb = c * 16 + q * 4;
                fma16(xv.x, &Ws[(kb + 0) * 4], a0, a1, a2, a3);
                fma16(xv.y, &Ws[(kb + 1) * 4], a0, a1, a2, a3);
                fma16(xv.z, &Ws[(kb + 2) * 4], a0, a1, a2, a3);
                fma16(xv.w, &Ws[(kb + 3) * 4], a0, a1, a2, a3);
            }
        }
    }
    if (n >= N) return;
    float s = rsqrtf((float)(g_deg[n] + 1));
    g_dinv[n] = s;
    a0.x *= s; a0.y *= s; a0.z *= s; a0.w *= s;
    a1.x *= s; a1.y *= s; a1.z *= s; a1.w *= s;
    a2.x *= s; a2.y *= s; a2.z *= s; a2.w *= s;
    a3.x *= s; a3.y *= s; a3.z *= s; a3.w *= s;
    float4* h = &g_h1s[(size_t)n * 4];
    h[0] = a0; h[1] = a1; h[2] = a2; h[3] = a3;
}

// ---------------------------------------------------------------------------
// Gather 1: warp per node, 4 lanes/edge, unroll x2, packed f32x2 accumulate.
// h2s[n] = relu(dinv*acc + b1) * dinv.
__global__ void k_gather1(const float* __restrict__ b1, int N) {
    int wid_in_blk = threadIdx.x >> 5;
    int lane = threadIdx.x & 31;
    int n = blockIdx.x * 8 + wid_in_blk;
    if (n >= N) return;

    int end   = g_rowptr[n];          // post-fill rowptr = row end
    int deg   = g_deg[n];
    int start = end - deg;
    int sub = lane & 3, eo = lane >> 2;

    uint64_t a01 = 0, a23 = 0, c01 = 0, c23 = 0, t;
    int e = start + eo;
    for (; e + 8 < end; e += 16) {
        int sA = g_csrc[e];
        int sB = g_csrc[e + 8];
        float4 va = g_h1s[(size_t)sA * 4 + sub];
        float4 vb = g_h1s[(size_t)sB * 4 + sub];
        PACKX2(t, va.x, va.y); ADDX2(a01, a01, t);
        PACKX2(t, va.z, va.w); ADDX2(a23, a23, t);
        PACKX2(t, vb.x, vb.y); ADDX2(c01, c01, t);
        PACKX2(t, vb.z, vb.w); ADDX2(c23, c23, t);
    }
    if (e < end) {
        float4 va = g_h1s[(size_t)g_csrc[e] * 4 + sub];
        PACKX2(t, va.x, va.y); ADDX2(a01, a01, t);
        PACKX2(t, va.z, va.w); ADDX2(a23, a23, t);
    }
    ADDX2(a01, a01, c01);
    ADDX2(a23, a23, c23);
    float4 acc;
    UNPACKX2(acc.x, acc.y, a01);
    UNPACKX2(acc.z, acc.w, a23);

#pragma unroll
    for (int o = 4; o < 32; o <<= 1) {
        acc.x += __shfl_xor_sync(~0u, acc.x, o);
        acc.y += __shfl_xor_sync(~0u, acc.y, o);
        acc.z += __shfl_xor_sync(~0u, acc.z, o);
        acc.w += __shfl_xor_sync(~0u, acc.w, o);
    }
    float4 self = g_h1s[(size_t)n * 4 + sub];
    float s = g_dinv[n];
    float4 b = ((const float4*)b1)[sub];
    acc.x = fmaxf(fmaf(acc.x + self.x, s, b.x), 0.0f) * s;
    acc.y = fmaxf(fmaf(acc.y + self.y, s, b.y), 0.0f) * s;
    acc.z = fmaxf(fmaf(acc.z + self.z, s, b.z), 0.0f) * s;
    acc.w = fmaxf(fmaf(acc.w + self.w, s, b.w), 0.0f) * s;
    if (lane < 4)
        g_h2s[(size_t)n * 4 + lane] = acc;
}

// ---------------------------------------------------------------------------
// Gather 2 + GEMM2 fused: warp per node, packed f32x2 accumulate.
// Self-cleans g_deg (restores 0 for next replay).
__global__ void k_gather2(const float* __restrict__ W2, const float* __restrict__ b2,
                          float* __restrict__ out, int N) {
    __shared__ float4 W2s[16 * 32];   // 16 x 128 floats
    for (int i = threadIdx.x; i < 512; i += 256)
        W2s[i] = ((const float4*)W2)[i];
    __syncthreads();

    int wid_in_blk = threadIdx.x >> 5;
    int lane = threadIdx.x & 31;
    int n = blockIdx.x * 8 + wid_in_blk;
    if (n >= N) return;

    int end   = g_rowptr[n];
    int deg   = g_deg[n];
    if (lane == 0) g_deg[n] = 0;      // restore zero for next replay
    int start = end - deg;
    int sub = lane & 3, eo = lane >> 2;

    uint64_t a01 = 0, a23 = 0, c01 = 0, c23 = 0, t;
    int e = start + eo;
    for (; e + 8 < end; e += 16) {
        int sA = g_csrc[e];
        int sB = g_csrc[e + 8];
        float4 va = g_h2s[(size_t)sA * 4 + sub];
        float4 vb = g_h2s[(size_t)sB * 4 + sub];
        PACKX2(t, va.x, va.y); ADDX2(a01, a01, t);
        PACKX2(t, va.z, va.w); ADDX2(a23, a23, t);
        PACKX2(t, vb.x, vb.y); ADDX2(c01, c01, t);
        PACKX2(t, vb.z, vb.w); ADDX2(c23, c23, t);
    }
    if (e < end) {
        float4 va = g_h2s[(size_t)g_csrc[e] * 4 + sub];
        PACKX2(t, va.x, va.y); ADDX2(a01, a01, t);
        PACKX2(t, va.z, va.w); ADDX2(a23, a23, t);
    }
    ADDX2(a01, a01, c01);
    ADDX2(a23, a23, c23);
    float4 acc;
    UNPACKX2(acc.x, acc.y, a01);
    UNPACKX2(acc.z, acc.w, a23);

#pragma unroll
    for (int o = 4; o < 32; o <<= 1) {
        acc.x += __shfl_xor_sync(~0u, acc.x, o);
        acc.y += __shfl_xor_sync(~0u, acc.y, o);
        acc.z += __shfl_xor_sync(~0u, acc.z, o);
        acc.w += __shfl_xor_sync(~0u, acc.w, o);
    }
    float4 self = g_h2s[(size_t)n * 4 + sub];
    float s = g_dinv[n];
    acc.x = (acc.x + self.x) * s;
    acc.y = (acc.y + self.y) * s;
    acc.z = (acc.z + self.z) * s;
    acc.w = (acc.w + self.w) * s;

    float av[16];
#pragma unroll
    for (int g = 0; g < 4; g++) {
        av[g * 4 + 0] = __shfl_sync(~0u, acc.x, g);
        av[g * 4 + 1] = __shfl_sync(~0u, acc.y, g);
        av[g * 4 + 2] = __shfl_sync(~0u, acc.z, g);
        av[g * 4 + 3] = __shfl_sync(~0u, acc.w, g);
    }

    float4 o4 = ((const float4*)b2)[lane];
#pragma unroll
    for (int f = 0; f < 16; f++) {
        float4 w = W2s[f * 32 + lane];
        o4.x += av[f] * w.x;
        o4.y += av[f] * w.y;
        o4.z += av[f] * w.z;
        o4.w += av[f] * w.w;
    }
    ((float4*)out)[(size_t)n * 32 + lane] = o4;
}

// ---------------------------------------------------------------------------
extern "C" void kernel_launch(void* const* d_in, const int* in_sizes, int n_in,
                              void* d_out, int out_size) {
    const float* x  = (const float*)d_in[0];
    const int*   ei = (const int*)d_in[1];     // int32 (JAX x64 disabled)
    const float* W1 = (const float*)d_in[2];
    const float* b1 = (const float*)d_in[3];
    const float* W2 = (const float*)d_in[4];
    const float* b2 = (const float*)d_in[5];
    float*       out = (float*)d_out;

    int N = in_sizes[0] / 128;
    int E = in_sizes[1] / 2;
    const int* src = ei;
    const int* dst = ei + E;

    const int TB = 256;
    int nb_N  = (N + TB - 1) / TB;
    int nb_E4 = (E / 4 + TB) / TB;   // 4 edges per thread (+ tail slack)

    // Streams/events created ONCE on the first (pre-baseline) invocation.
    static cudaStream_t sA = nullptr, sB = nullptr;
    static cudaEvent_t  eFork = nullptr, eA = nullptr, eB = nullptr;
    if (sA == nullptr) {
        cudaStreamCreateWithFlags(&sA, cudaStreamNonBlocking);
        cudaStreamCreateWithFlags(&sB, cudaStreamNonBlocking);
        cudaEventCreateWithFlags(&eFork, cudaEventDisableTiming);
        cudaEventCreateWithFlags(&eA, cudaEventDisableTiming);
        cudaEventCreateWithFlags(&eB, cudaEventDisableTiming);
    }

    // common prefix (g_deg is zero: BSS at load, self-cleaned each replay)
    k_deg<<<nb_E4, TB>>>(dst, E);
    cudaEventRecord(eFork, 0);

    // stream A: gemm1 (computes dinv internally from g_deg)
    cudaStreamWaitEvent(sA, eFork, 0);
    k_gemm1<<<nb_N, TB, 0, sA>>>(x, W1, N);

    // stream B: rowptr scan + CSR fill
    cudaStreamWaitEvent(sB, eFork, 0);
    k_scan1<<<nb_N, TB, 0, sB>>>(N);
    k_scan2<<<1, 512, 0, sB>>>(nb_N);
    k_finish<<<nb_N, TB, 0, sB>>>(N);
    k_fill<<<nb_E4, TB, 0, sB>>>(src, dst, E);

    // join
    cudaEventRecord(eA, sA);
    cudaEventRecord(eB, sB);
    cudaStreamWaitEvent(0, eA, 0);
    cudaStreamWaitEvent(0, eB, 0);

    // layer 1 aggregate + layer 2 aggregate (+ fused GEMM2)
    k_gather1<<<(N + 7) / 8, TB>>>(b1, N);
    k_gather2<<<(N + 7) / 8, TB>>>(W2, b2, out, N);
}

// round 14
// speedup vs baseline: 1.0693x; 1.0693x over previous
#include <cuda_runtime.h>
#include <stdint.h>

// Problem shape (fixed): N=100000, E=3200000, C_in=128, C_hid=16, C_out=128
#define MAXN 100096
#define MAXE 3400000

// Device scratch (static; no allocations). g_deg is zero at load (BSS) and
// restored to zero by k_gather2 every invocation (self-cleaning).
__device__ int    g_deg[MAXN];        // dst in-degree (no self loop)
__device__ int    g_rowptr[MAXN];     // CSR row start; after k_fill = row END
__device__ int    g_bsum[512];        // scan block sums
__device__ int    g_csrc[MAXE];       // CSR: src node per edge, grouped by dst
__device__ float  g_dinv[MAXN];       // 1/sqrt(deg+1)
__device__ float4 g_h1s[MAXN * 4];    // (X @ W1) * dinv      (16 f/node)
__device__ float4 g_h2s[MAXN * 4];    // relu(dinv*agg1 + b1) * dinv

// ---------------------------------------------------------------------------
// 4 edges per thread via int4 (higher atomic MLP, fewer index loads)
__global__ void k_deg(const int* __restrict__ dst, int E) {
    int i = blockIdx.x * blockDim.x + threadIdx.x;
    int base = i * 4;
    if (base + 3 < E) {
        int4 d = *(const int4*)(dst + base);
        atomicAdd(&g_deg[d.x], 1);
        atomicAdd(&g_deg[d.y], 1);
        atomicAdd(&g_deg[d.z], 1);
        atomicAdd(&g_deg[d.w], 1);
    } else if (base < E) {
        for (int j = base; j < E; j++) atomicAdd(&g_deg[dst[j]], 1);
    }
}

// Block-level exclusive scan (256/block) -> rowptr partial + per-block totals
__global__ void k_scan1(int N) {
    __shared__ int ws[8];
    int i = blockIdx.x * 256 + threadIdx.x;
    int lane = threadIdx.x & 31, wid = threadIdx.x >> 5;
    int v = (i < N) ? g_deg[i] : 0;
    int x = v;
#pragma unroll
    for (int o = 1; o < 32; o <<= 1) {
        int y = __shfl_up_sync(~0u, x, o);
        if (lane >= o) x += y;
    }
    if (lane == 31) ws[wid] = x;
    __syncthreads();
    if (wid == 0) {
        int s = (lane < 8) ? ws[lane] : 0;
#pragma unroll
        for (int o = 1; o < 8; o <<= 1) {
            int y = __shfl_up_sync(~0u, s, o);
            if (lane >= o) s += y;
        }
        if (lane < 8) ws[lane] = s;
    }
    __syncthreads();
    int excl = x - v + (wid ? ws[wid - 1] : 0);
    if (i < N) g_rowptr[i] = excl;
    if (threadIdx.x == 255) g_bsum[blockIdx.x] = ws[7];
}

// Scan the (<=512) block sums, single block.
__global__ void k_scan2(int nb) {
    __shared__ int sm[512];
    int t = threadIdx.x;
    int orig = (t < nb) ? g_bsum[t] : 0;
    sm[t] = orig;
    __syncthreads();
    for (int o = 1; o < 512; o <<= 1) {
        int v = (t >= o) ? sm[t - o] : 0;
        __syncthreads();
        sm[t] += v;
        __syncthreads();
    }
    if (t < nb) g_bsum[t] = sm[t] - orig;
}

// rowptr += block offset (k_fill will advance rowptr itself to row end)
__global__ void k_finish(int N) {
    int i = blockIdx.x * 256 + threadIdx.x;
    if (i < N) g_rowptr[i] += g_bsum[blockIdx.x];
}

// 4 edges per thread via int4; advances g_rowptr (post-fill: rowptr = row end)
__global__ void k_fill(const int* __restrict__ src, const int* __restrict__ dst, int E) {
    int i = blockIdx.x * blockDim.x + threadIdx.x;
    int base = i * 4;
    if (base + 3 < E) {
        int4 s = *(const int4*)(src + base);
        int4 d = *(const int4*)(dst + base);
        int p0 = atomicAdd(&g_rowptr[d.x], 1);
        int p1 = atomicAdd(&g_rowptr[d.y], 1);
        int p2 = atomicAdd(&g_rowptr[d.z], 1);
        int p3 = atomicAdd(&g_rowptr[d.w], 1);
        g_csrc[p0] = s.x;
        g_csrc[p1] = s.y;
        g_csrc[p2] = s.z;
        g_csrc[p3] = s.w;
    } else if (base < E) {
        for (int j = base; j < E; j++) {
            int pos = atomicAdd(&g_rowptr[dst[j]], 1);
            g_csrc[pos] = src[j];
        }
    }
}

// ---------------------------------------------------------------------------
// h1s = (X @ W1) * dinv; also computes g_dinv from g_deg (k_dinv folded in).
__device__ __forceinline__ void fma16(float xs, const float4* __restrict__ w,
                                      float4& a0, float4& a1, float4& a2, float4& a3) {
    float4 w0 = w[0], w1 = w[1], w2 = w[2], w3 = w[3];
    a0.x += xs * w0.x; a0.y += xs * w0.y; a0.z += xs * w0.z; a0.w += xs * w0.w;
    a1.x += xs * w1.x; a1.y += xs * w1.y; a1.z += xs * w1.z; a1.w += xs * w1.w;
    a2.x += xs * w2.x; a2.y += xs * w2.y; a2.z += xs * w2.z; a2.w += xs * w2.w;
    a3.x += xs * w3.x; a3.y += xs * w3.y; a3.z += xs * w3.z; a3.w += xs * w3.w;
}

__global__ void __launch_bounds__(256, 5)
k_gemm1(const float* __restrict__ x, const float* __restrict__ W1, int N) {
    __shared__ float4 Ws[512];        // 128 x 16
    __shared__ float4 Xs[256][5];     // 256 rows x 16 floats (+pad)

    for (int i = threadIdx.x; i < 512; i += 256)
        Ws[i] = ((const float4*)W1)[i];

    int n0 = blockIdx.x * 256;
    int rows = min(256, N - n0);
    int n = n0 + threadIdx.x;
    float4 a0 = {0,0,0,0}, a1 = a0, a2 = a0, a3 = a0;
    const float4* xg = (const float4*)x;

#pragma unroll 1
    for (int c = 0; c < 8; c++) {
        __syncthreads();
#pragma unroll
        for (int i = threadIdx.x; i < 1024; i += 256) {
            int r = i >> 2, q = i & 3;
            if (r < rows)
                Xs[r][q] = xg[(size_t)(n0 + r) * 32 + c * 4 + q];
        }
        __syncthreads();
        if (threadIdx.x < rows) {
#pragma unroll
            for (int q = 0; q < 4; q++) {
                float4 xv = Xs[threadIdx.x][q];
                int kb = c * 16 + q * 4;
                fma16(xv.x, &Ws[(kb + 0) * 4], a0, a1, a2, a3);
                fma16(xv.y, &Ws[(kb + 1) * 4], a0, a1, a2, a3);
                fma16(xv.z, &Ws[(kb + 2) * 4], a0, a1, a2, a3);
                fma16(xv.w, &Ws[(kb + 3) * 4], a0, a1, a2, a3);
            }
        }
    }
    if (n >= N) return;
    float s = rsqrtf((float)(g_deg[n] + 1));
    g_dinv[n] = s;
    a0.x *= s; a0.y *= s; a0.z *= s; a0.w *= s;
    a1.x *= s; a1.y *= s; a1.z *= s; a1.w *= s;
    a2.x *= s; a2.y *= s; a2.z *= s; a2.w *= s;
    a3.x *= s; a3.y *= s; a3.z *= s; a3.w *= s;
    float4* h = &g_h1s[(size_t)n * 4];
    h[0] = a0; h[1] = a1; h[2] = a2; h[3] = a3;
}

// ---------------------------------------------------------------------------
// Gather 1: warp per node. acc = h1s[n] + sum_{e in row} h1s[csrc[e]];
// h2s[n] = relu(dinv*acc + b1) * dinv.  4 lanes per edge; 2 edges in flight
// per lane (unroll x2). Scalar FADD accumulate (proven R9 form).
__global__ void k_gather1(const float* __restrict__ b1, int N) {
    int wid_in_blk = threadIdx.x >> 5;
    int lane = threadIdx.x & 31;
    int n = blockIdx.x * 8 + wid_in_blk;
    if (n >= N) return;

    int end   = g_rowptr[n];          // post-fill rowptr = row end
    int deg   = g_deg[n];
    int start = end - deg;
    int sub = lane & 3, eo = lane >> 2;

    float4 acc = {0, 0, 0, 0}, accB = {0, 0, 0, 0};
    int e = start + eo;
    for (; e + 8 < end; e += 16) {
        int sA = g_csrc[e];
        int sB = g_csrc[e + 8];
        float4 va = g_h1s[(size_t)sA * 4 + sub];
        float4 vb = g_h1s[(size_t)sB * 4 + sub];
        acc.x  += va.x; acc.y  += va.y; acc.z  += va.z; acc.w  += va.w;
        accB.x += vb.x; accB.y += vb.y; accB.z += vb.z; accB.w += vb.w;
    }
    if (e < end) {
        float4 va = g_h1s[(size_t)g_csrc[e] * 4 + sub];
        acc.x += va.x; acc.y += va.y; acc.z += va.z; acc.w += va.w;
    }
    acc.x += accB.x; acc.y += accB.y; acc.z += accB.z; acc.w += accB.w;

#pragma unroll
    for (int o = 4; o < 32; o <<= 1) {
        acc.x += __shfl_xor_sync(~0u, acc.x, o);
        acc.y += __shfl_xor_sync(~0u, acc.y, o);
        acc.z += __shfl_xor_sync(~0u, acc.z, o);
        acc.w += __shfl_xor_sync(~0u, acc.w, o);
    }
    float4 self = g_h1s[(size_t)n * 4 + sub];
    float s = g_dinv[n];
    float4 b = ((const float4*)b1)[sub];
    acc.x = fmaxf(fmaf(acc.x + self.x, s, b.x), 0.0f) * s;
    acc.y = fmaxf(fmaf(acc.y + self.y, s, b.y), 0.0f) * s;
    acc.z = fmaxf(fmaf(acc.z + self.z, s, b.z), 0.0f) * s;
    acc.w = fmaxf(fmaf(acc.w + self.w, s, b.w), 0.0f) * s;
    if (lane < 4)
        g_h2s[(size_t)n * 4 + lane] = acc;
}

// ---------------------------------------------------------------------------
// Gather 2 + GEMM2 fused: warp per node (unroll x2, scalar accumulate).
// Self-cleans g_deg (restores 0 for next replay).
__global__ void k_gather2(const float* __restrict__ W2, const float* __restrict__ b2,
                          float* __restrict__ out, int N) {
    __shared__ float4 W2s[16 * 32];   // 16 x 128 floats
    for (int i = threadIdx.x; i < 512; i += 256)
        W2s[i] = ((const float4*)W2)[i];
    __syncthreads();

    int wid_in_blk = threadIdx.x >> 5;
    int lane = threadIdx.x & 31;
    int n = blockIdx.x * 8 + wid_in_blk;
    if (n >= N) return;

    int end   = g_rowptr[n];
    int deg   = g_deg[n];
    if (lane == 0) g_deg[n] = 0;      // restore zero for next replay
    int start = end - deg;
    int sub = lane & 3, eo = lane >> 2;

    float4 acc = {0, 0, 0, 0}, accB = {0, 0, 0, 0};
    int e = start + eo;
    for (; e + 8 < end; e += 16) {
        int sA = g_csrc[e];
        int sB = g_csrc[e + 8];
        float4 va = g_h2s[(size_t)sA * 4 + sub];
        float4 vb = g_h2s[(size_t)sB * 4 + sub];
        acc.x  += va.x; acc.y  += va.y; acc.z  += va.z; acc.w  += va.w;
        accB.x += vb.x; accB.y += vb.y; accB.z += vb.z; accB.w += vb.w;
    }
    if (e < end) {
        float4 va = g_h2s[(size_t)g_csrc[e] * 4 + sub];
        acc.x += va.x; acc.y += va.y; acc.z += va.z; acc.w += va.w;
    }
    acc.x += accB.x; acc.y += accB.y; acc.z += accB.z; acc.w += accB.w;

#pragma unroll
    for (int o = 4; o < 32; o <<= 1) {
        acc.x += __shfl_xor_sync(~0u, acc.x, o);
        acc.y += __shfl_xor_sync(~0u, acc.y, o);
        acc.z += __shfl_xor_sync(~0u, acc.z, o);
        acc.w += __shfl_xor_sync(~0u, acc.w, o);
    }
    float4 self = g_h2s[(size_t)n * 4 + sub];
    float s = g_dinv[n];
    acc.x = (acc.x + self.x) * s;
    acc.y = (acc.y + self.y) * s;
    acc.z = (acc.z + self.z) * s;
    acc.w = (acc.w + self.w) * s;

    float av[16];
#pragma unroll
    for (int g = 0; g < 4; g++) {
        av[g * 4 + 0] = __shfl_sync(~0u, acc.x, g);
        av[g * 4 + 1] = __shfl_sync(~0u, acc.y, g);
        av[g * 4 + 2] = __shfl_sync(~0u, acc.z, g);
        av[g * 4 + 3] = __shfl_sync(~0u, acc.w, g);
    }

    float4 o4 = ((const float4*)b2)[lane];
#pragma unroll
    for (int f = 0; f < 16; f++) {
        float4 w = W2s[f * 32 + lane];
        o4.x += av[f] * w.x;
        o4.y += av[f] * w.y;
        o4.z += av[f] * w.z;
        o4.w += av[f] * w.w;
    }
    ((float4*)out)[(size_t)n * 32 + lane] = o4;
}

// ---------------------------------------------------------------------------
extern "C" void kernel_launch(void* const* d_in, const int* in_sizes, int n_in,
                              void* d_out, int out_size) {
    const float* x  = (const float*)d_in[0];
    const int*   ei = (const int*)d_in[1];     // int32 (JAX x64 disabled)
    const float* W1 = (const float*)d_in[2];
    const float* b1 = (const float*)d_in[3];
    const float* W2 = (const float*)d_in[4];
    const float* b2 = (const float*)d_in[5];
    float*       out = (float*)d_out;

    int N = in_sizes[0] / 128;
    int E = in_sizes[1] / 2;
    const int* src = ei;
    const int* dst = ei + E;

    const int TB = 256;
    int nb_N  = (N + TB - 1) / TB;
    int nb_E4 = (E / 4 + TB) / TB;   // 4 edges per thread (+ tail slack)

    // Streams/events created ONCE on the first (pre-baseline) invocation.
    static cudaStream_t sA = nullptr, sB = nullptr;
    static cudaEvent_t  eFork = nullptr, eA = nullptr, eB = nullptr;
    if (sA == nullptr) {
        cudaStreamCreateWithFlags(&sA, cudaStreamNonBlocking);
        cudaStreamCreateWithFlags(&sB, cudaStreamNonBlocking);
        cudaEventCreateWithFlags(&eFork, cudaEventDisableTiming);
        cudaEventCreateWithFlags(&eA, cudaEventDisableTiming);
        cudaEventCreateWithFlags(&eB, cudaEventDisableTiming);
    }

    // common prefix (g_deg is zero: BSS at load, self-cleaned each replay)
    k_deg<<<nb_E4, TB>>>(dst, E);
    cudaEventRecord(eFork, 0);

    // stream A: gemm1 (computes dinv internally from g_deg)
    cudaStreamWaitEvent(sA, eFork, 0);
    k_gemm1<<<nb_N, TB, 0, sA>>>(x, W1, N);

    // stream B: rowptr scan + CSR fill
    cudaStreamWaitEvent(sB, eFork, 0);
    k_scan1<<<nb_N, TB, 0, sB>>>(N);
    k_scan2<<<1, 512, 0, sB>>>(nb_N);
    k_finish<<<nb_N, TB, 0, sB>>>(N);
    k_fill<<<nb_E4, TB, 0, sB>>>(src, dst, E);

    // join
    cudaEventRecord(eA, sA);
    cudaEventRecord(eB, sB);
    cudaStreamWaitEvent(0, eA, 0);
    cudaStreamWaitEvent(0, eB, 0);

    // layer 1 aggregate + layer 2 aggregate (+ fused GEMM2)
    k_gather1<<<(N + 7) / 8, TB>>>(b1, N);
    k_gather2<<<(N + 7) / 8, TB>>>(W2, b2, out, N);
}

// round 15
// speedup vs baseline: 1.6083x; 1.5040x over previous
#include <cuda_runtime.h>
#include <stdint.h>

// Problem shape (fixed): N=100000, E=3200000, C_in=128, C_hid=16, C_out=128
#define MAXN 100096
#define MAXE 3400000

// Device scratch (static; no allocations allowed).
__device__ int    g_deg[MAXN];        // dst in-degree (no self loop)
__device__ int    g_rowptr[MAXN];     // CSR row starts (exclusive scan of deg)
__device__ int    g_cursor[MAXN];     // fill cursors
__device__ int    g_bsum[512];        // scan block sums
__device__ int    g_csrc[MAXE];       // CSR: src node per edge, grouped by dst
__device__ float  g_dinv[MAXN];       // 1/sqrt(deg+1)
__device__ float4 g_h1s[MAXN * 4];    // (X @ W1) * dinv      (16 f/node)
__device__ float4 g_h2s[MAXN * 4];    // relu(dinv*agg1 + b1) * dinv

// ---------------------------------------------------------------------------
__global__ void k_zero(int N) {
    int i = blockIdx.x * blockDim.x + threadIdx.x;
    if (i < N) g_deg[i] = 0;
}

// 4 edges per thread via int4 (higher atomic MLP, fewer index loads)
__global__ void k_deg(const int* __restrict__ dst, int E) {
    int i = blockIdx.x * blockDim.x + threadIdx.x;
    int base = i * 4;
    if (base + 3 < E) {
        int4 d = *(const int4*)(dst + base);
        atomicAdd(&g_deg[d.x], 1);
        atomicAdd(&g_deg[d.y], 1);
        atomicAdd(&g_deg[d.z], 1);
        atomicAdd(&g_deg[d.w], 1);
    } else if (base < E) {
        for (int j = base; j < E; j++) atomicAdd(&g_deg[dst[j]], 1);
    }
}

__global__ void k_dinv(int N) {
    int i = blockIdx.x * blockDim.x + threadIdx.x;
    if (i < N) g_dinv[i] = rsqrtf((float)(g_deg[i] + 1));
}

// Block-level exclusive scan (256/block) -> rowptr partial + per-block totals
__global__ void k_scan1(int N) {
    __shared__ int ws[8];
    int i = blockIdx.x * 256 + threadIdx.x;
    int lane = threadIdx.x & 31, wid = threadIdx.x >> 5;
    int v = (i < N) ? g_deg[i] : 0;
    int x = v;
#pragma unroll
    for (int o = 1; o < 32; o <<= 1) {
        int y = __shfl_up_sync(~0u, x, o);
        if (lane >= o) x += y;
    }
    if (lane == 31) ws[wid] = x;
    __syncthreads();
    if (wid == 0) {
        int s = (lane < 8) ? ws[lane] : 0;
#pragma unroll
        for (int o = 1; o < 8; o <<= 1) {
            int y = __shfl_up_sync(~0u, s, o);
            if (lane >= o) s += y;
        }
        if (lane < 8) ws[lane] = s;
    }
    __syncthreads();
    int excl = x - v + (wid ? ws[wid - 1] : 0);
    if (i < N) g_rowptr[i] = excl;
    if (threadIdx.x == 255) g_bsum[blockIdx.x] = ws[7];
}

// Scan the (<=512) block sums, single block.
__global__ void k_scan2(int nb) {
    __shared__ int sm[512];
    int t = threadIdx.x;
    int orig = (t < nb) ? g_bsum[t] : 0;
    sm[t] = orig;
    __syncthreads();
    for (int o = 1; o < 512; o <<= 1) {
        int v = (t >= o) ? sm[t - o] : 0;
        __syncthreads();
        sm[t] += v;
        __syncthreads();
    }
    if (t < nb) g_bsum[t] = sm[t] - orig;
}

// rowptr += block offset; cursor = rowptr
__global__ void k_finish(int N) {
    int i = blockIdx.x * 256 + threadIdx.x;
    if (i >= N) return;
    int rp = g_rowptr[i] + g_bsum[blockIdx.x];
    g_rowptr[i] = rp;
    g_cursor[i] = rp;
}

// 4 edges per thread via int4
__global__ void k_fill(const int* __restrict__ src, const int* __restrict__ dst, int E) {
    int i = blockIdx.x * blockDim.x + threadIdx.x;
    int base = i * 4;
    if (base + 3 < E) {
        int4 s = *(const int4*)(src + base);
        int4 d = *(const int4*)(dst + base);
        int p0 = atomicAdd(&g_cursor[d.x], 1);
        int p1 = atomicAdd(&g_cursor[d.y], 1);
        int p2 = atomicAdd(&g_cursor[d.z], 1);
        int p3 = atomicAdd(&g_cursor[d.w], 1);
        g_csrc[p0] = s.x;
        g_csrc[p1] = s.y;
        g_csrc[p2] = s.z;
        g_csrc[p3] = s.w;
    } else if (base < E) {
        for (int j = base; j < E; j++) {
            int pos = atomicAdd(&g_cursor[dst[j]], 1);
            g_csrc[pos] = src[j];
        }
    }
}

// ---------------------------------------------------------------------------
// h1s = (X @ W1) * dinv. X staged through smem in 16-float chunks.
__device__ __forceinline__ void fma16(float xs, const float4* __restrict__ w,
                                      float4& a0, float4& a1, float4& a2, float4& a3) {
    float4 w0 = w[0], w1 = w[1], w2 = w[2], w3 = w[3];
    a0.x += xs * w0.x; a0.y += xs * w0.y; a0.z += xs * w0.z; a0.w += xs * w0.w;
    a1.x += xs * w1.x; a1.y += xs * w1.y; a1.z += xs * w1.z; a1.w += xs * w1.w;
    a2.x += xs * w2.x; a2.y += xs * w2.y; a2.z += xs * w2.z; a2.w += xs * w2.w;
    a3.x += xs * w3.x; a3.y += xs * w3.y; a3.z += xs * w3.z; a3.w += xs * w3.w;
}

__global__ void __launch_bounds__(256, 5)
k_gemm1(const float* __restrict__ x, const float* __restrict__ W1, int N) {
    __shared__ float4 Ws[512];        // 128 x 16
    __shared__ float4 Xs[256][5];     // 256 rows x 16 floats (+pad)

    for (int i = threadIdx.x; i < 512; i += 256)
        Ws[i] = ((const float4*)W1)[i];

    int n0 = blockIdx.x * 256;
    int rows = min(256, N - n0);
    int n = n0 + threadIdx.x;
    float4 a0 = {0,0,0,0}, a1 = a0, a2 = a0, a3 = a0;
    const float4* xg = (const float4*)x;

#pragma unroll 1
    for (int c = 0; c < 8; c++) {
        __syncthreads();
#pragma unroll
        for (int i = threadIdx.x; i < 1024; i += 256) {
            int r = i >> 2, q = i & 3;
            if (r < rows)
                Xs[r][q] = xg[(size_t)(n0 + r) * 32 + c * 4 + q];
        }
        __syncthreads();
        if (threadIdx.x < rows) {
#pragma unroll
            for (int q = 0; q < 4; q++) {
                float4 xv = Xs[threadIdx.x][q];
                int kb = c * 16 + q * 4;
                fma16(xv.x, &Ws[(kb + 0) * 4], a0, a1, a2, a3);
                fma16(xv.y, &Ws[(kb + 1) * 4], a0, a1, a2, a3);
                fma16(xv.z, &Ws[(kb + 2) * 4], a0, a1, a2, a3);
                fma16(xv.w, &Ws[(kb + 3) * 4], a0, a1, a2, a3);
            }
        }
    }
    if (n >= N) return;
    float s = g_dinv[n];
    a0.x *= s; a0.y *= s; a0.z *= s; a0.w *= s;
    a1.x *= s; a1.y *= s; a1.z *= s; a1.w *= s;
    a2.x *= s; a2.y *= s; a2.z *= s; a2.w *= s;
    a3.x *= s; a3.y *= s; a3.z *= s; a3.w *= s;
    float4* h = &g_h1s[(size_t)n * 4];
    h[0] = a0; h[1] = a1; h[2] = a2; h[3] = a3;
}

// ---------------------------------------------------------------------------
// Gather 1: warp per node. acc = h1s[n] + sum_{e in row} h1s[csrc[e]];
// h2s[n] = relu(dinv*acc + b1) * dinv.  4 lanes per edge; 2 edges in flight
// per lane (unroll x2) to raise MLP on the random L2-hit gathers.
__global__ void k_gather1(const float* __restrict__ b1, int N) {
    int wid_in_blk = threadIdx.x >> 5;
    int lane = threadIdx.x & 31;
    int n = blockIdx.x * 8 + wid_in_blk;
    if (n >= N) return;

    int start = g_rowptr[n];
    int deg   = g_deg[n];
    int end   = start + deg;
    int sub = lane & 3, eo = lane >> 2;

    float4 acc = {0, 0, 0, 0}, accB = {0, 0, 0, 0};
    int e = start + eo;
    for (; e + 8 < end; e += 16) {
        int sA = g_csrc[e];
        int sB = g_csrc[e + 8];
        float4 va = g_h1s[(size_t)sA * 4 + sub];
        float4 vb = g_h1s[(size_t)sB * 4 + sub];
        acc.x  += va.x; acc.y  += va.y; acc.z  += va.z; acc.w  += va.w;
        accB.x += vb.x; accB.y += vb.y; accB.z += vb.z; accB.w += vb.w;
    }
    if (e < end) {
        float4 va = g_h1s[(size_t)g_csrc[e] * 4 + sub];
        acc.x += va.x; acc.y += va.y; acc.z += va.z; acc.w += va.w;
    }
    acc.x += accB.x; acc.y += accB.y; acc.z += accB.z; acc.w += accB.w;

#pragma unroll
    for (int o = 4; o < 32; o <<= 1) {
        acc.x += __shfl_xor_sync(~0u, acc.x, o);
        acc.y += __shfl_xor_sync(~0u, acc.y, o);
        acc.z += __shfl_xor_sync(~0u, acc.z, o);
        acc.w += __shfl_xor_sync(~0u, acc.w, o);
    }
    float4 self = g_h1s[(size_t)n * 4 + sub];
    float s = g_dinv[n];
    float4 b = ((const float4*)b1)[sub];
    acc.x = fmaxf(fmaf(acc.x + self.x, s, b.x), 0.0f) * s;
    acc.y = fmaxf(fmaf(acc.y + self.y, s, b.y), 0.0f) * s;
    acc.z = fmaxf(fmaf(acc.z + self.z, s, b.z), 0.0f) * s;
    acc.w = fmaxf(fmaf(acc.w + self.w, s, b.w), 0.0f) * s;
    if (lane < 4)
        g_h2s[(size_t)n * 4 + lane] = acc;
}

// ---------------------------------------------------------------------------
// Gather 2 + GEMM2 fused: warp per node (unroll x2 gather).
// a = dinv * (h2s[n] + sum h2s[csrc[e]]);  out[n] = a @ W2 + b2.
__global__ void k_gather2(const float* __restrict__ W2, const float* __restrict__ b2,
                          float* __restrict__ out, int N) {
    __shared__ float4 W2s[16 * 32];   // 16 x 128 floats
    for (int i = threadIdx.x; i < 512; i += 256)
        W2s[i] = ((const float4*)W2)[i];
    __syncthreads();

    int wid_in_blk = threadIdx.x >> 5;
    int lane = threadIdx.x & 31;
    int n = blockIdx.x * 8 + wid_in_blk;
    if (n >= N) return;

    int start = g_rowptr[n];
    int deg   = g_deg[n];
    int end   = start + deg;
    int sub = lane & 3, eo = lane >> 2;

    float4 acc = {0, 0, 0, 0}, accB = {0, 0, 0, 0};
    int e = start + eo;
    for (; e + 8 < end; e += 16) {
        int sA = g_csrc[e];
        int sB = g_csrc[e + 8];
        float4 va = g_h2s[(size_t)sA * 4 + sub];
        float4 vb = g_h2s[(size_t)sB * 4 + sub];
        acc.x  += va.x; acc.y  += va.y; acc.z  += va.z; acc.w  += va.w;
        accB.x += vb.x; accB.y += vb.y; accB.z += vb.z; accB.w += vb.w;
    }
    if (e < end) {
        float4 va = g_h2s[(size_t)g_csrc[e] * 4 + sub];
        acc.x += va.x; acc.y += va.y; acc.z += va.z; acc.w += va.w;
    }
    acc.x += accB.x; acc.y += accB.y; acc.z += accB.z; acc.w += accB.w;

#pragma unroll
    for (int o = 4; o < 32; o <<= 1) {
        acc.x += __shfl_xor_sync(~0u, acc.x, o);
        acc.y += __shfl_xor_sync(~0u, acc.y, o);
        acc.z += __shfl_xor_sync(~0u, acc.z, o);
        acc.w += __shfl_xor_sync(~0u, acc.w, o);
    }
    float4 self = g_h2s[(size_t)n * 4 + sub];
    float s = g_dinv[n];
    acc.x = (acc.x + self.x) * s;
    acc.y = (acc.y + self.y) * s;
    acc.z = (acc.z + self.z) * s;
    acc.w = (acc.w + self.w) * s;

    float av[16];
#pragma unroll
    for (int g = 0; g < 4; g++) {
        av[g * 4 + 0] = __shfl_sync(~0u, acc.x, g);
        av[g * 4 + 1] = __shfl_sync(~0u, acc.y, g);
        av[g * 4 + 2] = __shfl_sync(~0u, acc.z, g);
        av[g * 4 + 3] = __shfl_sync(~0u, acc.w, g);
    }

    float4 o4 = ((const float4*)b2)[lane];
#pragma unroll
    for (int f = 0; f < 16; f++) {
        float4 w = W2s[f * 32 + lane];
        o4.x += av[f] * w.x;
        o4.y += av[f] * w.y;
        o4.z += av[f] * w.z;
        o4.w += av[f] * w.w;
    }
    ((float4*)out)[(size_t)n * 32 + lane] = o4;
}

// ---------------------------------------------------------------------------
extern "C" void kernel_launch(void* const* d_in, const int* in_sizes, int n_in,
                              void* d_out, int out_size) {
    const float* x  = (const float*)d_in[0];
    const int*   ei = (const int*)d_in[1];     // int32 (JAX x64 disabled)
    const float* b1 = (const float*)d_in[3];
    const float* W1 = (const float*)d_in[2];
    const float* W2 = (const float*)d_in[4];
    const float* b2 = (const float*)d_in[5];
    float*       out = (float*)d_out;

    int N = in_sizes[0] / 128;
    int E = in_sizes[1] / 2;
    const int* src = ei;
    const int* dst = ei + E;

    const int TB = 256;
    int nb_N  = (N + TB - 1) / TB;
    int nb_E4 = (E / 4 + TB) / TB;   // 4 edges per thread (+ tail slack)

    // Streams/events created ONCE on the first (pre-baseline) invocation.
    static cudaStream_t sA = nullptr, sB = nullptr;
    static cudaEvent_t  eFork = nullptr, eA = nullptr, eB = nullptr;
    if (sA == nullptr) {
        cudaStreamCreateWithFlags(&sA, cudaStreamNonBlocking);
        cudaStreamCreateWithFlags(&sB, cudaStreamNonBlocking);
        cudaEventCreateWithFlags(&eFork, cudaEventDisableTiming);
        cudaEventCreateWithFlags(&eA, cudaEventDisableTiming);
        cudaEventCreateWithFlags(&eB, cudaEventDisableTiming);
    }

    // common prefix (capture/base stream)
    k_zero<<<nb_N, TB>>>(N);
    k_deg<<<nb_E4, TB>>>(dst, E);
    cudaEventRecord(eFork, 0);

    // stream A: dinv -> gemm1  (independent of the CSR scan/fill)
    cudaStreamWaitEvent(sA, eFork, 0);
    k_dinv<<<nb_N, TB, 0, sA>>>(N);
    k_gemm1<<<nb_N, TB, 0, sA>>>(x, W1, N);

    // stream B: rowptr scan + CSR fill
    cudaStreamWaitEvent(sB, eFork, 0);
    k_scan1<<<nb_N, TB, 0, sB>>>(N);
    k_scan2<<<1, 512, 0, sB>>>(nb_N);
    k_finish<<<nb_N, TB, 0, sB>>>(N);
    k_fill<<<nb_E4, TB, 0, sB>>>(src, dst, E);

    // join
    cudaEventRecord(eA, sA);
    cudaEventRecord(eB, sB);
    cudaStreamWaitEvent(0, eA, 0);
    cudaStreamWaitEvent(0, eB, 0);

    // layer 1 aggregate + layer 2 aggregate (+ fused GEMM2)
    k_gather1<<<(N + 7) / 8, TB>>>(b1, N);
    k_gather2<<<(N + 7) / 8, TB>>>(W2, b2, out, N);
}

// round 16
// speedup vs baseline: 1.6095x; 1.0007x over previous
#include <cuda_runtime.h>
#include <stdint.h>

// Problem shape (fixed): N=100000, E=3200000, C_in=128, C_hid=16, C_out=128
#define MAXN 100096
#define MAXE 3400000

// Device scratch (static; no allocations allowed).
__device__ int    g_deg[MAXN];        // dst in-degree (no self loop)
__device__ int    g_rowptr[MAXN];     // CSR row starts (exclusive scan of deg)
__device__ int    g_cursor[MAXN];     // fill cursors
__device__ int    g_bsum[512];        // scan block sums
__device__ int    g_csrc[MAXE];       // CSR: src node per edge, grouped by dst
__device__ float  g_dinv[MAXN];       // 1/sqrt(deg+1)
__device__ float4 g_h1s[MAXN * 4];    // (X @ W1) * dinv      (16 f/node)
__device__ float4 g_h2s[MAXN * 4];    // relu(dinv*agg1 + b1) * dinv

// ---------------------------------------------------------------------------
// 4 edges per thread via int4 (higher atomic MLP, fewer index loads)
__global__ void k_deg(const int* __restrict__ dst, int E) {
    int i = blockIdx.x * blockDim.x + threadIdx.x;
    int base = i * 4;
    if (base + 3 < E) {
        int4 d = *(const int4*)(dst + base);
        atomicAdd(&g_deg[d.x], 1);
        atomicAdd(&g_deg[d.y], 1);
        atomicAdd(&g_deg[d.z], 1);
        atomicAdd(&g_deg[d.w], 1);
    } else if (base < E) {
        for (int j = base; j < E; j++) atomicAdd(&g_deg[dst[j]], 1);
    }
}

__global__ void k_dinv(int N) {
    int i = blockIdx.x * blockDim.x + threadIdx.x;
    if (i < N) g_dinv[i] = rsqrtf((float)(g_deg[i] + 1));
}

// Block-level exclusive scan (256/block) -> rowptr partial + per-block totals
__global__ void k_scan1(int N) {
    __shared__ int ws[8];
    int i = blockIdx.x * 256 + threadIdx.x;
    int lane = threadIdx.x & 31, wid = threadIdx.x >> 5;
    int v = (i < N) ? g_deg[i] : 0;
    int x = v;
#pragma unroll
    for (int o = 1; o < 32; o <<= 1) {
        int y = __shfl_up_sync(~0u, x, o);
        if (lane >= o) x += y;
    }
    if (lane == 31) ws[wid] = x;
    __syncthreads();
    if (wid == 0) {
        int s = (lane < 8) ? ws[lane] : 0;
#pragma unroll
        for (int o = 1; o < 8; o <<= 1) {
            int y = __shfl_up_sync(~0u, s, o);
            if (lane >= o) s += y;
        }
        if (lane < 8) ws[lane] = s;
    }
    __syncthreads();
    int excl = x - v + (wid ? ws[wid - 1] : 0);
    if (i < N) g_rowptr[i] = excl;
    if (threadIdx.x == 255) g_bsum[blockIdx.x] = ws[7];
}

// Scan the (<=512) block sums, single block.
__global__ void k_scan2(int nb) {
    __shared__ int sm[512];
    int t = threadIdx.x;
    int orig = (t < nb) ? g_bsum[t] : 0;
    sm[t] = orig;
    __syncthreads();
    for (int o = 1; o < 512; o <<= 1) {
        int v = (t >= o) ? sm[t - o] : 0;
        __syncthreads();
        sm[t] += v;
        __syncthreads();
    }
    if (t < nb) g_bsum[t] = sm[t] - orig;
}

// rowptr += block offset; cursor = rowptr
__global__ void k_finish(int N) {
    int i = blockIdx.x * 256 + threadIdx.x;
    if (i >= N) return;
    int rp = g_rowptr[i] + g_bsum[blockIdx.x];
    g_rowptr[i] = rp;
    g_cursor[i] = rp;
}

// 4 edges per thread via int4
__global__ void k_fill(const int* __restrict__ src, const int* __restrict__ dst, int E) {
    int i = blockIdx.x * blockDim.x + threadIdx.x;
    int base = i * 4;
    if (base + 3 < E) {
        int4 s = *(const int4*)(src + base);
        int4 d = *(const int4*)(dst + base);
        int p0 = atomicAdd(&g_cursor[d.x], 1);
        int p1 = atomicAdd(&g_cursor[d.y], 1);
        int p2 = atomicAdd(&g_cursor[d.z], 1);
        int p3 = atomicAdd(&g_cursor[d.w], 1);
        g_csrc[p0] = s.x;
        g_csrc[p1] = s.y;
        g_csrc[p2] = s.z;
        g_csrc[p3] = s.w;
    } else if (base < E) {
        for (int j = base; j < E; j++) {
            int pos = atomicAdd(&g_cursor[dst[j]], 1);
            g_csrc[pos] = src[j];
        }
    }
}

// ---------------------------------------------------------------------------
// h1s = (X @ W1) * dinv. X staged through smem in 16-float chunks.
__device__ __forceinline__ void fma16(float xs, const float4* __restrict__ w,
                                      float4& a0, float4& a1, float4& a2, float4& a3) {
    float4 w0 = w[0], w1 = w[1], w2 = w[2], w3 = w[3];
    a0.x += xs * w0.x; a0.y += xs * w0.y; a0.z += xs * w0.z; a0.w += xs * w0.w;
    a1.x += xs * w1.x; a1.y += xs * w1.y; a1.z += xs * w1.z; a1.w += xs * w1.w;
    a2.x += xs * w2.x; a2.y += xs * w2.y; a2.z += xs * w2.z; a2.w += xs * w2.w;
    a3.x += xs * w3.x; a3.y += xs * w3.y; a3.z += xs * w3.z; a3.w += xs * w3.w;
}

__global__ void __launch_bounds__(256, 5)
k_gemm1(const float* __restrict__ x, const float* __restrict__ W1, int N) {
    __shared__ float4 Ws[512];        // 128 x 16
    __shared__ float4 Xs[256][5];     // 256 rows x 16 floats (+pad)

    for (int i = threadIdx.x; i < 512; i += 256)
        Ws[i] = ((const float4*)W1)[i];

    int n0 = blockIdx.x * 256;
    int rows = min(256, N - n0);
    int n = n0 + threadIdx.x;
    float4 a0 = {0,0,0,0}, a1 = a0, a2 = a0, a3 = a0;
    const float4* xg = (const float4*)x;

#pragma unroll 1
    for (int c = 0; c < 8; c++) {
        __syncthreads();
#pragma unroll
        for (int i = threadIdx.x; i < 1024; i += 256) {
            int r = i >> 2, q = i & 3;
            if (r < rows)
                Xs[r][q] = xg[(size_t)(n0 + r) * 32 + c * 4 + q];
        }
        __syncthreads();
        if (threadIdx.x < rows) {
#pragma unroll
            for (int q = 0; q < 4; q++) {
                float4 xv = Xs[threadIdx.x][q];
                int kb = c * 16 + q * 4;
                fma16(xv.x, &Ws[(kb + 0) * 4], a0, a1, a2, a3);
                fma16(xv.y, &Ws[(kb + 1) * 4], a0, a1, a2, a3);
                fma16(xv.z, &Ws[(kb + 2) * 4], a0, a1, a2, a3);
                fma16(xv.w, &Ws[(kb + 3) * 4], a0, a1, a2, a3);
            }
        }
    }
    if (n >= N) return;
    float s = g_dinv[n];
    a0.x *= s; a0.y *= s; a0.z *= s; a0.w *= s;
    a1.x *= s; a1.y *= s; a1.z *= s; a1.w *= s;
    a2.x *= s; a2.y *= s; a2.z *= s; a2.w *= s;
    a3.x *= s; a3.y *= s; a3.z *= s; a3.w *= s;
    float4* h = &g_h1s[(size_t)n * 4];
    h[0] = a0; h[1] = a1; h[2] = a2; h[3] = a3;
}

// ---------------------------------------------------------------------------
// Gather 1: warp per node. acc = h1s[n] + sum_{e in row} h1s[csrc[e]];
// h2s[n] = relu(dinv*acc + b1) * dinv.  4 lanes per edge; 2 edges in flight
// per lane (unroll x2) to raise MLP on the random L2-hit gathers.
__global__ void k_gather1(const float* __restrict__ b1, int N) {
    int wid_in_blk = threadIdx.x >> 5;
    int lane = threadIdx.x & 31;
    int n = blockIdx.x * 8 + wid_in_blk;
    if (n >= N) return;

    int start = g_rowptr[n];
    int deg   = g_deg[n];
    int end   = start + deg;
    int sub = lane & 3, eo = lane >> 2;

    float4 acc = {0, 0, 0, 0}, accB = {0, 0, 0, 0};
    int e = start + eo;
    for (; e + 8 < end; e += 16) {
        int sA = g_csrc[e];
        int sB = g_csrc[e + 8];
        float4 va = g_h1s[(size_t)sA * 4 + sub];
        float4 vb = g_h1s[(size_t)sB * 4 + sub];
        acc.x  += va.x; acc.y  += va.y; acc.z  += va.z; acc.w  += va.w;
        accB.x += vb.x; accB.y += vb.y; accB.z += vb.z; accB.w += vb.w;
    }
    if (e < end) {
        float4 va = g_h1s[(size_t)g_csrc[e] * 4 + sub];
        acc.x += va.x; acc.y += va.y; acc.z += va.z; acc.w += va.w;
    }
    acc.x += accB.x; acc.y += accB.y; acc.z += accB.z; acc.w += accB.w;

#pragma unroll
    for (int o = 4; o < 32; o <<= 1) {
        acc.x += __shfl_xor_sync(~0u, acc.x, o);
        acc.y += __shfl_xor_sync(~0u, acc.y, o);
        acc.z += __shfl_xor_sync(~0u, acc.z, o);
        acc.w += __shfl_xor_sync(~0u, acc.w, o);
    }
    float4 self = g_h1s[(size_t)n * 4 + sub];
    float s = g_dinv[n];
    float4 b = ((const float4*)b1)[sub];
    acc.x = fmaxf(fmaf(acc.x + self.x, s, b.x), 0.0f) * s;
    acc.y = fmaxf(fmaf(acc.y + self.y, s, b.y), 0.0f) * s;
    acc.z = fmaxf(fmaf(acc.z + self.z, s, b.z), 0.0f) * s;
    acc.w = fmaxf(fmaf(acc.w + self.w, s, b.w), 0.0f) * s;
    if (lane < 4)
        g_h2s[(size_t)n * 4 + lane] = acc;
}

// ---------------------------------------------------------------------------
// Gather 2 + GEMM2 fused: warp per node (unroll x2 gather).
// a = dinv * (h2s[n] + sum h2s[csrc[e]]);  out[n] = a @ W2 + b2.
__global__ void k_gather2(const float* __restrict__ W2, const float* __restrict__ b2,
                          float* __restrict__ out, int N) {
    __shared__ float4 W2s[16 * 32];   // 16 x 128 floats
    for (int i = threadIdx.x; i < 512; i += 256)
        W2s[i] = ((const float4*)W2)[i];
    __syncthreads();

    int wid_in_blk = threadIdx.x >> 5;
    int lane = threadIdx.x & 31;
    int n = blockIdx.x * 8 + wid_in_blk;
    if (n >= N) return;

    int start = g_rowptr[n];
    int deg   = g_deg[n];
    int end   = start + deg;
    int sub = lane & 3, eo = lane >> 2;

    float4 acc = {0, 0, 0, 0}, accB = {0, 0, 0, 0};
    int e = start + eo;
    for (; e + 8 < end; e += 16) {
        int sA = g_csrc[e];
        int sB = g_csrc[e + 8];
        float4 va = g_h2s[(size_t)sA * 4 + sub];
        float4 vb = g_h2s[(size_t)sB * 4 + sub];
        acc.x  += va.x; acc.y  += va.y; acc.z  += va.z; acc.w  += va.w;
        accB.x += vb.x; accB.y += vb.y; accB.z += vb.z; accB.w += vb.w;
    }
    if (e < end) {
        float4 va = g_h2s[(size_t)g_csrc[e] * 4 + sub];
        acc.x += va.x; acc.y += va.y; acc.z += va.z; acc.w += va.w;
    }
    acc.x += accB.x; acc.y += accB.y; acc.z += accB.z; acc.w += accB.w;

#pragma unroll
    for (int o = 4; o < 32; o <<= 1) {
        acc.x += __shfl_xor_sync(~0u, acc.x, o);
        acc.y += __shfl_xor_sync(~0u, acc.y, o);
        acc.z += __shfl_xor_sync(~0u, acc.z, o);
        acc.w += __shfl_xor_sync(~0u, acc.w, o);
    }
    float4 self = g_h2s[(size_t)n * 4 + sub];
    float s = g_dinv[n];
    acc.x = (acc.x + self.x) * s;
    acc.y = (acc.y + self.y) * s;
    acc.z = (acc.z + self.z) * s;
    acc.w = (acc.w + self.w) * s;

    float av[16];
#pragma unroll
    for (int g = 0; g < 4; g++) {
        av[g * 4 + 0] = __shfl_sync(~0u, acc.x, g);
        av[g * 4 + 1] = __shfl_sync(~0u, acc.y, g);
        av[g * 4 + 2] = __shfl_sync(~0u, acc.z, g);
        av[g * 4 + 3] = __shfl_sync(~0u, acc.w, g);
    }

    float4 o4 = ((const float4*)b2)[lane];
#pragma unroll
    for (int f = 0; f < 16; f++) {
        float4 w = W2s[f * 32 + lane];
        o4.x += av[f] * w.x;
        o4.y += av[f] * w.y;
        o4.z += av[f] * w.z;
        o4.w += av[f] * w.w;
    }
    ((float4*)out)[(size_t)n * 32 + lane] = o4;
}

// ---------------------------------------------------------------------------
extern "C" void kernel_launch(void* const* d_in, const int* in_sizes, int n_in,
                              void* d_out, int out_size) {
    const float* x  = (const float*)d_in[0];
    const int*   ei = (const int*)d_in[1];     // int32 (JAX x64 disabled)
    const float* W1 = (const float*)d_in[2];
    const float* b1 = (const float*)d_in[3];
    const float* W2 = (const float*)d_in[4];
    const float* b2 = (const float*)d_in[5];
    float*       out = (float*)d_out;

    int N = in_sizes[0] / 128;
    int E = in_sizes[1] / 2;
    const int* src = ei;
    const int* dst = ei + E;

    const int TB = 256;
    int nb_N  = (N + TB - 1) / TB;
    int nb_E4 = (E / 4 + TB) / TB;   // 4 edges per thread (+ tail slack)

    // Streams/events created ONCE on the first (pre-baseline) invocation.
    static cudaStream_t sA = nullptr, sB = nullptr;
    static cudaEvent_t  eFork = nullptr, eA = nullptr, eB = nullptr;
    static void* degPtr = nullptr;
    if (sA == nullptr) {
        cudaStreamCreateWithFlags(&sA, cudaStreamNonBlocking);
        cudaStreamCreateWithFlags(&sB, cudaStreamNonBlocking);
        cudaEventCreateWithFlags(&eFork, cudaEventDisableTiming);
        cudaEventCreateWithFlags(&eA, cudaEventDisableTiming);
        cudaEventCreateWithFlags(&eB, cudaEventDisableTiming);
        cudaGetSymbolAddress(&degPtr, g_deg);
    }

    // common prefix (capture/base stream): memset node instead of k_zero kernel
    cudaMemsetAsync(degPtr, 0, (size_t)N * sizeof(int), 0);
    k_deg<<<nb_E4, TB>>>(dst, E);
    cudaEventRecord(eFork, 0);

    // stream A: dinv -> gemm1  (independent of the CSR scan/fill)
    cudaStreamWaitEvent(sA, eFork, 0);
    k_dinv<<<nb_N, TB, 0, sA>>>(N);
    k_gemm1<<<nb_N, TB, 0, sA>>>(x, W1, N);

    // stream B: rowptr scan + CSR fill
    cudaStreamWaitEvent(sB, eFork, 0);
    k_scan1<<<nb_N, TB, 0, sB>>>(N);
    k_scan2<<<1, 512, 0, sB>>>(nb_N);
    k_finish<<<nb_N, TB, 0, sB>>>(N);
    k_fill<<<nb_E4, TB, 0, sB>>>(src, dst, E);

    // join
    cudaEventRecord(eA, sA);
    cudaEventRecord(eB, sB);
    cudaStreamWaitEvent(0, eA, 0);
    cudaStreamWaitEvent(0, eB, 0);

    // layer 1 aggregate + layer 2 aggregate (+ fused GEMM2)
    k_gather1<<<(N + 7) / 8, TB>>>(b1, N);
    k_gather2<<<(N + 7) / 8, TB>>>(W2, b2, out, N);
}